// round 15
// baseline (speedup 1.0000x reference)
#include <cuda_runtime.h>
#include <cuda_fp16.h>
#include <cuda_bf16.h>
#include <cstdint>

// ---------------- problem constants ----------------
#define NQ      1024      // 64 batches * 16 slots
#define MCW     16001     // codebook rows
#define MPAD    16128     // 126 * 128 = 168 * 96
#define KDIM    2016
#define BM      64        // q rows per CTA
#define BN      96        // m cols per CTA
#define BK      32        // halfs per k stage
#define NKITER  63        // 2016 / 32
#define SEGLEN  3         // k-iters per accumulation segment (63 = 21*3)
#define GT      384       // gemm threads (12 warps)

// dtype codes
#define DT_F16  0
#define DT_BF16 1
#define DT_F32  2

// ---------------- scratch (static device memory; no allocs) ----------------
__device__ int    g_dt_x;
__device__ int    g_dt_d;
__device__ __half g_xq[NQ * KDIM];           // permuted queries, k-major
__device__ __half g_cb[(size_t)MPAD * KDIM]; // codebook fp16 (rows >= MCW stay zero)
__device__ float  g_xs[NQ];
__device__ float  g_x2[NQ];
__device__ float  g_c2[MPAD];
__device__ float  g_cn2[MPAD];
__device__ unsigned long long g_m0[NQ];      // packed (key(d0)<<32 | idx) running min
__device__ unsigned long long g_m1[NQ];      // packed (key(d1)<<32 | idx) running min

// ---------------- small PTX helpers ----------------
__device__ __forceinline__ uint32_t smem_u32(const void* p) {
    uint32_t a;
    asm("{ .reg .u64 t; cvta.to.shared.u64 t, %1; cvt.u32.u64 %0, t; }" : "=r"(a) : "l"(p));
    return a;
}
__device__ __forceinline__ void cp16(uint32_t dst, const void* src) {
    asm volatile("cp.async.cg.shared.global [%0], [%1], 16;\n" :: "r"(dst), "l"(src));
}
__device__ __forceinline__ void cp_commit() { asm volatile("cp.async.commit_group;\n"); }
__device__ __forceinline__ void ldsm4(uint32_t* r, uint32_t addr) {
    asm volatile("ldmatrix.sync.aligned.m8n8.x4.shared.b16 {%0,%1,%2,%3}, [%4];"
                 : "=r"(r[0]), "=r"(r[1]), "=r"(r[2]), "=r"(r[3]) : "r"(addr));
}
__device__ __forceinline__ void mma16816(float* d, const uint32_t* a, uint32_t b0, uint32_t b1) {
    asm volatile("mma.sync.aligned.m16n8k16.row.col.f32.f16.f16.f32 "
                 "{%0,%1,%2,%3}, {%4,%5,%6,%7}, {%8,%9}, {%0,%1,%2,%3};\n"
                 : "+f"(d[0]), "+f"(d[1]), "+f"(d[2]), "+f"(d[3])
                 : "r"(a[0]), "r"(a[1]), "r"(a[2]), "r"(a[3]), "r"(b0), "r"(b1));
}
// order-preserving float->u32 key (monotone for all floats incl. negatives)
__device__ __forceinline__ uint32_t fkey(float f) {
    uint32_t b = __float_as_uint(f);
    return (b & 0x80000000u) ? ~b : (b | 0x80000000u);
}

// ---------------- generic 8-element load ----------------
__device__ __forceinline__ void load8(const void* p, size_t off, int dt, float* f) {
    if (dt == DT_F32) {
        const float4* q = (const float4*)((const float*)p + off);
        float4 v0 = q[0], v1 = q[1];
        f[0]=v0.x; f[1]=v0.y; f[2]=v0.z; f[3]=v0.w;
        f[4]=v1.x; f[5]=v1.y; f[6]=v1.z; f[7]=v1.w;
    } else if (dt == DT_F16) {
        uint4 v = *(const uint4*)((const __half*)p + off);
        const __half2* hp = (const __half2*)&v;
#pragma unroll
        for (int i = 0; i < 4; i++) {
            float2 g = __half22float2(hp[i]);
            f[2*i] = g.x; f[2*i+1] = g.y;
        }
    } else {
        uint4 v = *(const uint4*)((const __nv_bfloat16*)p + off);
        const __nv_bfloat162* hp = (const __nv_bfloat162*)&v;
#pragma unroll
        for (int i = 0; i < 4; i++) {
            float2 g = __bfloat1622float2(hp[i]);
            f[2*i] = g.x; f[2*i+1] = g.y;
        }
    }
}

// ---------------- kernel 0: dtype detection + packed-min reset ----------------
// (merged so the gemm kernel is the 4th launch -> gets profiled by ncu -s/-c)
__global__ void detect_kernel(const uint32_t* x, const uint32_t* d) {
    const int gi = blockIdx.x * blockDim.x + threadIdx.x;
    if (gi < NQ) { g_m0[gi] = ~0ull; g_m1[gi] = ~0ull; }
    if (gi == 0) {
        const uint32_t* ps[2] = {x, d};
        int* outs[2] = {&g_dt_x, &g_dt_d};
        for (int a = 0; a < 2; a++) {
            uint32_t lowmax = 0, highmax = 0;
            for (int i = 0; i < 64; i++) {
                uint32_t w = ps[a][i];
                uint32_t lo = w & 0xFFFFu, hi = w >> 16;
                if (lo > lowmax) lowmax = lo;
                if (hi > highmax) highmax = hi;
            }
            int dt;
            if (lowmax >= 0x4000u)       dt = DT_F32;
            else if (highmax >= 0x3C00u) dt = DT_BF16;
            else                         dt = DT_F16;
            *outs[a] = dt;
        }
    }
}

// ---------------- kernel 1: permute x -> xq (fp16), compute xs/x2 ----------------
__global__ __launch_bounds__(256) void build_xq_kernel(const void* xraw) {
    const int q = blockIdx.x;
    const int b = q >> 4, slot = q & 15;
    const int t = threadIdx.x;
    const int dt = g_dt_x;
    float s = 0.f, s2 = 0.f;
    if (t < 252) {
        const int ch = t / 126, row = t % 126;
        const size_t off = (size_t)b * 32256 + ch * 16128 + row * 128 + slot * 8;
        float f[8];
        load8(xraw, off, dt, f);
        __half h[8];
#pragma unroll
        for (int i = 0; i < 8; i++) {
            h[i] = __float2half_rn(f[i]);
            s  += f[i];
            s2 += f[i] * f[i];
        }
        *(uint4*)(g_xq + (size_t)q * KDIM + t * 8) = *(const uint4*)h;
    }
    __shared__ float r0[256], r1[256];
    r0[t] = s; r1[t] = s2; __syncthreads();
    for (int st = 128; st > 0; st >>= 1) {
        if (t < st) { r0[t] += r0[t + st]; r1[t] += r1[t + st]; }
        __syncthreads();
    }
    if (t == 0) { g_xs[q] = r0[0]; g_x2[q] = r1[0]; }
}

// ---------------- kernel 2: codebook -> fp16 + per-row c2/cn2 ----------------
__global__ __launch_bounds__(128) void prep_cb_kernel(const void* draw) {
    const int m = blockIdx.x;
    const int t = threadIdx.x;
    const int dt = g_dt_d;
    __half* dst = g_cb + (size_t)m * KDIM;
    float s2 = 0.f, sn2 = 0.f;
    for (int v = t; v < 252; v += 128) {
        float f[8];
        load8(draw, (size_t)m * KDIM + v * 8, dt, f);
        __half h[8];
#pragma unroll
        for (int i = 0; i < 8; i++) {
            h[i] = __float2half_rn(f[i]);
            s2 += f[i] * f[i];
            float g1 = 1.0f - f[i];
            sn2 += g1 * g1;
        }
        *(uint4*)(dst + v * 8) = *(const uint4*)h;
    }
    __shared__ float r0[128], r1[128];
    r0[t] = s2; r1[t] = sn2; __syncthreads();
    for (int st = 64; st > 0; st >>= 1) {
        if (t < st) { r0[t] += r0[t + st]; r1[t] += r1[t + st]; }
        __syncthreads();
    }
    if (t == 0) { g_c2[m] = r0[0]; g_cn2[m] = r1[0]; }
}

// ---------------- kernel 3: GEMM + fused distance/argmin ----------------
// CTA tile 64q x 96m, 384 threads / 12 warps (warp tile 32q x 16m, 2q x 6n
// warp grid), 3-stage cp.async pipeline, 2 CTAs/SM (same 24 warps/SM as R14
// but -17% L2 row traffic and -33% CTA count). Numerics bit-identical to the
// R6/R14 passes: per-3-iter MMA segments Kahan-folded with __fadd_rn/__fsub_rn.
// Epilogue: d0/d1 from in-register xc (same op order), packed (key|idx) u64
// min via smem atomicMin_block then one global atomicMin per (q,dist) per CTA.
#define APITCH 40
#define A_STAGE (BM * APITCH)             // 2560 halfs
#define B_STAGE (BN * APITCH)             // 3840 halfs
#define A_STAGE_BYTES (A_STAGE * 2)       // 5120 B
#define B_STAGE_BYTES (B_STAGE * 2)       // 7680 B

__global__ __launch_bounds__(GT, 2) void gemm_kernel() {
    __shared__ __half sA[3][A_STAGE];
    __shared__ __half sB[3][B_STAGE];
    __shared__ unsigned long long s_min0[BM];
    __shared__ unsigned long long s_min1[BM];

    const int tile_m = blockIdx.x * BM;    // q tile (x fastest: q-tiles share cb rows in L2)
    const int tile_n = blockIdx.y * BN;    // m tile
    const int tid  = threadIdx.x;
    const int wid  = tid >> 5;
    const int lane = tid & 31;
    const int warp_q = wid & 1;    // 2 q-groups of 32
    const int warp_n = wid >> 1;   // 6 n-groups of 16

    const uint32_t sA_u = smem_u32(&sA[0][0]);
    const uint32_t sB_u = smem_u32(&sB[0][0]);

    // global-load mapping: B row for all 384 threads (96 rows), A row for tid<256
    const int rowL = tid >> 2;             // 0..95
    const int ka   = (tid & 3) * 8;
    const __half* gA = g_xq + (size_t)(tile_m + rowL) * KDIM + ka;  // deref only tid<256
    const __half* gB = g_cb + (size_t)(tile_n + rowL) * KDIM + ka;
    const uint32_t dA = sA_u + ((rowL * APITCH + ka) << 1);
    const uint32_t dB = sB_u + ((rowL * APITCH + ka) << 1);

    float sum[2][2][4], comp[2][2][4], chunk[2][2][4];
#pragma unroll
    for (int i = 0; i < 2; i++)
#pragma unroll
        for (int j = 0; j < 2; j++)
#pragma unroll
            for (int k = 0; k < 4; k++) { sum[i][j][k] = 0.f; comp[i][j][k] = 0.f; chunk[i][j][k] = 0.f; }

    // ldmatrix per-lane addressing (identical scheme to the R14 pass)
    const int arow  = warp_q * 32 + (lane & 15);
    const int akoff = (lane >> 4) << 3;
    const int bn    = warp_n * 16 + (lane & 7) + ((lane >> 4) << 3);
    const int bkoff = lane & 8;

    // prologue: stages 0, 1
#pragma unroll
    for (int s = 0; s < 2; s++) {
        const int k0 = s * BK;
        if (tid < 256) cp16(dA + s * A_STAGE_BYTES, gA + k0);
        cp16(dB + s * B_STAGE_BYTES, gB + k0);
        cp_commit();
    }

    for (int kt = 0; kt < NKITER; kt++) {
        // pending groups before this wait: G_kt, G_{kt+1}; at kt==62 only G_62.
        if (kt < NKITER - 1) asm volatile("cp.async.wait_group 1;\n");
        else                 asm volatile("cp.async.wait_group 0;\n");
        __syncthreads();   // also protects buffer (kt+2)%3 (consumed at kt-1) for reuse

        // issue loads for stage kt+2 into the freed buffer, then compute
        if (kt + 2 < NKITER) {
            const int nbuf = (kt + 2) % 3;
            const int k0 = (kt + 2) * BK;
            if (tid < 256) cp16(dA + nbuf * A_STAGE_BYTES, gA + k0);
            cp16(dB + nbuf * B_STAGE_BYTES, gB + k0);
            cp_commit();
        }

        const int buf = kt % 3;
        const uint32_t aB = sA_u + buf * A_STAGE_BYTES;
        const uint32_t bB = sB_u + buf * B_STAGE_BYTES;
#pragma unroll
        for (int ks = 0; ks < 2; ks++) {
            const int kh = ks * 16;
            uint32_t ra[2][4], rb[4];
            uint32_t a0 = aB + ((arow * APITCH + kh + akoff) << 1);
            ldsm4(ra[0], a0);
            ldsm4(ra[1], a0 + (16 * APITCH << 1));
            ldsm4(rb, bB + ((bn * APITCH + kh + bkoff) << 1));
#pragma unroll
            for (int mt = 0; mt < 2; mt++)
#pragma unroll
                for (int nt = 0; nt < 2; nt++)
                    mma16816(chunk[mt][nt], ra[mt], rb[nt * 2], rb[nt * 2 + 1]);
        }

        if ((kt % SEGLEN) == (SEGLEN - 1)) {
#pragma unroll
            for (int mt = 0; mt < 2; mt++)
#pragma unroll
                for (int nt = 0; nt < 2; nt++)
#pragma unroll
                    for (int e = 0; e < 4; e++) {
                        float y = __fsub_rn(chunk[mt][nt][e], comp[mt][nt][e]);
                        float tt = __fadd_rn(sum[mt][nt][e], y);
                        comp[mt][nt][e] = __fsub_rn(__fsub_rn(tt, sum[mt][nt][e]), y);
                        sum[mt][nt][e] = tt;
                        chunk[mt][nt][e] = 0.f;
                    }
        }
    }

    // -------- fused epilogue: distances + packed argmin --------
    for (int i = tid; i < BM; i += GT) { s_min0[i] = ~0ull; s_min1[i] = ~0ull; }
    __syncthreads();

    int   gm[2][2]; float vc2[2][2], vcn2[2][2]; bool mok[2][2];
#pragma unroll
    for (int nt = 0; nt < 2; nt++)
#pragma unroll
        for (int e1 = 0; e1 < 2; e1++) {
            int m = tile_n + warp_n * 16 + nt * 8 + (lane & 3) * 2 + e1;
            gm[nt][e1] = m;
            mok[nt][e1] = (m < MCW);
            vc2[nt][e1]  = mok[nt][e1] ? g_c2[m]  : 0.f;
            vcn2[nt][e1] = mok[nt][e1] ? g_cn2[m] : 0.f;
        }

#pragma unroll
    for (int mt = 0; mt < 2; mt++)
#pragma unroll
        for (int e2 = 0; e2 < 2; e2++) {
            const int qloc = warp_q * 32 + mt * 16 + (lane >> 2) + e2 * 8;
            const float x2v = g_x2[tile_m + qloc];
            const float xsv = g_xs[tile_m + qloc];
            unsigned long long b0 = ~0ull, b1 = ~0ull;
#pragma unroll
            for (int nt = 0; nt < 2; nt++)
#pragma unroll
                for (int e1 = 0; e1 < 2; e1++) {
                    if (!mok[nt][e1]) continue;
                    const int e = e2 * 2 + e1;
                    const float xc = __fadd_rn(sum[mt][nt][e], comp[mt][nt][e]);
                    const float d0 = __fsub_rn(__fadd_rn(x2v, vc2[nt][e1]), 2.0f * xc);
                    const float d1 = __fsub_rn(__fadd_rn(x2v, vcn2[nt][e1]),
                                               2.0f * __fsub_rn(xsv, xc));
                    unsigned long long p0 = ((unsigned long long)fkey(d0) << 32) | (uint32_t)gm[nt][e1];
                    unsigned long long p1 = ((unsigned long long)fkey(d1) << 32) | (uint32_t)gm[nt][e1];
                    if (p0 < b0) b0 = p0;
                    if (p1 < b1) b1 = p1;
                }
            atomicMin_block(&s_min0[qloc], b0);
            atomicMin_block(&s_min1[qloc], b1);
        }
    __syncthreads();

    if (tid < BM) {
        atomicMin(&g_m0[tile_m + tid], s_min0[tid]);
        atomicMin(&g_m1[tile_m + tid], s_min1[tid]);
    }
}

// ---------------- kernel 4: finalize -> bits ----------------
__global__ void finalize_kernel(float* __restrict__ out) {
    const int q = blockIdx.x * blockDim.x + threadIdx.x;
    if (q >= NQ) return;
    const unsigned long long v0 = g_m0[q];
    const unsigned long long v1 = g_m1[q];
    const uint32_t k0 = (uint32_t)(v0 >> 32);
    const uint32_t k1 = (uint32_t)(v1 >> 32);
    // [d0, d1, d1, d0] concat: d0 block first -> d0 wins ties
    const int res = (k0 <= k1) ? (int)(v0 & 0xFFFFFFFFu) : MCW + (int)(v1 & 0xFFFFFFFFu);
#pragma unroll
    for (int b = 0; b < 32; b++)
        out[q * 32 + b] = (float)((res >> b) & 1);
}

// ---------------- launch ----------------
extern "C" void kernel_launch(void* const* d_in, const int* in_sizes, int n_in,
                              void* d_out, int out_size) {
    // Identify inputs by element count, NOT by position:
    //   x    : 64*2*126*128   = 2,064,384
    //   data : 16001*2*126*8  = 32,258,016
    const void* x    = d_in[0];
    const void* data = d_in[1];
    if (n_in >= 2 && in_sizes[0] > in_sizes[1]) {
        x    = d_in[1];
        data = d_in[0];
    }
    float* out = (float*)d_out;   // [64,512], float 0.0/1.0

    detect_kernel<<<4, 256>>>((const uint32_t*)x, (const uint32_t*)data);
    build_xq_kernel<<<NQ, 256>>>(x);
    prep_cb_kernel<<<MCW, 128>>>(data);
    gemm_kernel<<<dim3(NQ / BM, MPAD / BN), GT>>>();   // 4th launch -> profiled
    finalize_kernel<<<4, 256>>>(out);
}

// round 16
// speedup vs baseline: 1.6209x; 1.6209x over previous
#include <cuda_runtime.h>
#include <cuda_fp16.h>
#include <cuda_bf16.h>
#include <cstdint>

// ---------------- problem constants ----------------
#define NQ      1024      // 64 batches * 16 slots
#define MCW     16001     // codebook rows
#define MPAD    16128     // 126 * 128
#define KDIM    2016
#define BM      64        // q rows per CTA
#define BN      64        // m cols per CTA
#define BK      32        // halfs per k stage
#define NKITER  63        // 2016 / 32
#define SEGLEN  3         // k-iters per accumulation segment (63 = 21*3)
#define NST     4         // pipeline stages

// dtype codes
#define DT_F16  0
#define DT_BF16 1
#define DT_F32  2

// ---------------- scratch (static device memory; no allocs) ----------------
__device__ int    g_dt_x;
__device__ int    g_dt_d;
__device__ __half g_xq[NQ * KDIM];           // permuted queries, k-major
__device__ __half g_cb[(size_t)MPAD * KDIM]; // codebook fp16 (rows >= MCW stay zero)
__device__ float  g_xs[NQ];
__device__ float  g_x2[NQ];
__device__ float  g_c2[MPAD];
__device__ float  g_cn2[MPAD];
__device__ unsigned long long g_m0[NQ];      // packed (key(d0)<<32 | idx) running min
__device__ unsigned long long g_m1[NQ];      // packed (key(d1)<<32 | idx) running min

// ---------------- small PTX helpers ----------------
__device__ __forceinline__ uint32_t smem_u32(const void* p) {
    uint32_t a;
    asm("{ .reg .u64 t; cvta.to.shared.u64 t, %1; cvt.u32.u64 %0, t; }" : "=r"(a) : "l"(p));
    return a;
}
__device__ __forceinline__ void cp16(uint32_t dst, const void* src) {
    asm volatile("cp.async.cg.shared.global [%0], [%1], 16;\n" :: "r"(dst), "l"(src));
}
__device__ __forceinline__ void cp_commit() { asm volatile("cp.async.commit_group;\n"); }
__device__ __forceinline__ void ldsm4(uint32_t* r, uint32_t addr) {
    asm volatile("ldmatrix.sync.aligned.m8n8.x4.shared.b16 {%0,%1,%2,%3}, [%4];"
                 : "=r"(r[0]), "=r"(r[1]), "=r"(r[2]), "=r"(r[3]) : "r"(addr));
}
__device__ __forceinline__ void mma16816(float* d, const uint32_t* a, uint32_t b0, uint32_t b1) {
    asm volatile("mma.sync.aligned.m16n8k16.row.col.f32.f16.f16.f32 "
                 "{%0,%1,%2,%3}, {%4,%5,%6,%7}, {%8,%9}, {%0,%1,%2,%3};\n"
                 : "+f"(d[0]), "+f"(d[1]), "+f"(d[2]), "+f"(d[3])
                 : "r"(a[0]), "r"(a[1]), "r"(a[2]), "r"(a[3]), "r"(b0), "r"(b1));
}
// order-preserving float->u32 key (monotone for all floats incl. negatives)
__device__ __forceinline__ uint32_t fkey(float f) {
    uint32_t b = __float_as_uint(f);
    return (b & 0x80000000u) ? ~b : (b | 0x80000000u);
}

// ---- packed f32x2 Kahan (bit-identical to the scalar __fsub_rn/__fadd_rn fold:
//      fma.rn(a,-1,b) has one rounding of b-a, exactly like sub.rn) ----
__device__ __forceinline__ uint64_t pack2(float lo, float hi) {
    uint64_t p;
    asm("mov.b64 %0, {%1, %2};" : "=l"(p) : "r"(__float_as_uint(lo)), "r"(__float_as_uint(hi)));
    return p;
}
__device__ __forceinline__ float2 unpack2(uint64_t p) {
    uint32_t lo, hi;
    asm("mov.b64 {%0, %1}, %2;" : "=r"(lo), "=r"(hi) : "l"(p));
    return make_float2(__uint_as_float(lo), __uint_as_float(hi));
}
__device__ __forceinline__ void kahan2(uint64_t& s, uint64_t& c, uint64_t ch, uint64_t neg1) {
    uint64_t y, t, d;
    asm("fma.rn.f32x2 %0, %1, %2, %3;" : "=l"(y) : "l"(c), "l"(neg1), "l"(ch));  // y = ch - c
    asm("add.rn.f32x2 %0, %1, %2;"     : "=l"(t) : "l"(s), "l"(y));              // t = s + y
    asm("fma.rn.f32x2 %0, %1, %2, %3;" : "=l"(d) : "l"(s), "l"(neg1), "l"(t));   // d = t - s
    asm("fma.rn.f32x2 %0, %1, %2, %3;" : "=l"(c) : "l"(y), "l"(neg1), "l"(d));   // c = d - y
    s = t;
}

// ---------------- generic 8-element load ----------------
__device__ __forceinline__ void load8(const void* p, size_t off, int dt, float* f) {
    if (dt == DT_F32) {
        const float4* q = (const float4*)((const float*)p + off);
        float4 v0 = q[0], v1 = q[1];
        f[0]=v0.x; f[1]=v0.y; f[2]=v0.z; f[3]=v0.w;
        f[4]=v1.x; f[5]=v1.y; f[6]=v1.z; f[7]=v1.w;
    } else if (dt == DT_F16) {
        uint4 v = *(const uint4*)((const __half*)p + off);
        const __half2* hp = (const __half2*)&v;
#pragma unroll
        for (int i = 0; i < 4; i++) {
            float2 g = __half22float2(hp[i]);
            f[2*i] = g.x; f[2*i+1] = g.y;
        }
    } else {
        uint4 v = *(const uint4*)((const __nv_bfloat16*)p + off);
        const __nv_bfloat162* hp = (const __nv_bfloat162*)&v;
#pragma unroll
        for (int i = 0; i < 4; i++) {
            float2 g = __bfloat1622float2(hp[i]);
            f[2*i] = g.x; f[2*i+1] = g.y;
        }
    }
}

// ---------------- kernel 0: dtype detection + packed-min reset ----------------
__global__ void detect_kernel(const uint32_t* x, const uint32_t* d) {
    const int gi = blockIdx.x * blockDim.x + threadIdx.x;
    if (gi < NQ) { g_m0[gi] = ~0ull; g_m1[gi] = ~0ull; }
    if (gi == 0) {
        const uint32_t* ps[2] = {x, d};
        int* outs[2] = {&g_dt_x, &g_dt_d};
        for (int a = 0; a < 2; a++) {
            uint32_t lowmax = 0, highmax = 0;
            for (int i = 0; i < 64; i++) {
                uint32_t w = ps[a][i];
                uint32_t lo = w & 0xFFFFu, hi = w >> 16;
                if (lo > lowmax) lowmax = lo;
                if (hi > highmax) highmax = hi;
            }
            int dt;
            if (lowmax >= 0x4000u)       dt = DT_F32;
            else if (highmax >= 0x3C00u) dt = DT_BF16;
            else                         dt = DT_F16;
            *outs[a] = dt;
        }
    }
}

// ---------------- kernel 1: permute x -> xq (fp16), compute xs/x2 ----------------
__global__ __launch_bounds__(256) void build_xq_kernel(const void* xraw) {
    const int q = blockIdx.x;
    const int b = q >> 4, slot = q & 15;
    const int t = threadIdx.x;
    const int dt = g_dt_x;
    float s = 0.f, s2 = 0.f;
    if (t < 252) {
        const int ch = t / 126, row = t % 126;
        const size_t off = (size_t)b * 32256 + ch * 16128 + row * 128 + slot * 8;
        float f[8];
        load8(xraw, off, dt, f);
        __half h[8];
#pragma unroll
        for (int i = 0; i < 8; i++) {
            h[i] = __float2half_rn(f[i]);
            s  += f[i];
            s2 += f[i] * f[i];
        }
        *(uint4*)(g_xq + (size_t)q * KDIM + t * 8) = *(const uint4*)h;
    }
    __shared__ float r0[256], r1[256];
    r0[t] = s; r1[t] = s2; __syncthreads();
    for (int st = 128; st > 0; st >>= 1) {
        if (t < st) { r0[t] += r0[t + st]; r1[t] += r1[t + st]; }
        __syncthreads();
    }
    if (t == 0) { g_xs[q] = r0[0]; g_x2[q] = r1[0]; }
}

// ---------------- kernel 2: codebook -> fp16 + per-row c2/cn2 ----------------
__global__ __launch_bounds__(128) void prep_cb_kernel(const void* draw) {
    const int m = blockIdx.x;
    const int t = threadIdx.x;
    const int dt = g_dt_d;
    __half* dst = g_cb + (size_t)m * KDIM;
    float s2 = 0.f, sn2 = 0.f;
    for (int v = t; v < 252; v += 128) {
        float f[8];
        load8(draw, (size_t)m * KDIM + v * 8, dt, f);
        __half h[8];
#pragma unroll
        for (int i = 0; i < 8; i++) {
            h[i] = __float2half_rn(f[i]);
            s2 += f[i] * f[i];
            float g1 = 1.0f - f[i];
            sn2 += g1 * g1;
        }
        *(uint4*)(dst + v * 8) = *(const uint4*)h;
    }
    __shared__ float r0[128], r1[128];
    r0[t] = s2; r1[t] = sn2; __syncthreads();
    for (int st = 64; st > 0; st >>= 1) {
        if (t < st) { r0[t] += r0[t + st]; r1[t] += r1[t + st]; }
        __syncthreads();
    }
    if (t == 0) { g_c2[m] = r0[0]; g_cn2[m] = r1[0]; }
}

// ---------------- kernel 3: GEMM + fused distance/argmin ----------------
// R14 winner config (64q x 64m, 256 thr / 8 warps, warp tile 32q x 16m,
// 3 CTAs/SM) + two upgrades:
//  (1) 4-stage cp.async pipeline (deeper load slack, fewer exposed waits)
//  (2) packed f32x2 Kahan fold (halves the scalar fma issue load;
//      bit-identical rounding to the scalar rn fold).
#define APITCH 40
#define A_STAGE (BM * APITCH)             // 2560 halfs
#define B_STAGE (BN * APITCH)
#define A_STAGE_BYTES (A_STAGE * 2)       // 5120 B
#define B_STAGE_BYTES (B_STAGE * 2)

__global__ __launch_bounds__(256, 3) void gemm_kernel() {
    __shared__ __half sA[NST][A_STAGE];
    __shared__ __half sB[NST][B_STAGE];
    __shared__ unsigned long long s_min0[BM];
    __shared__ unsigned long long s_min1[BM];

    const int tile_m = blockIdx.x * BM;    // q tile (x fastest: q-tiles share cb rows in L2)
    const int tile_n = blockIdx.y * BN;    // m tile
    const int tid  = threadIdx.x;
    const int wid  = tid >> 5;
    const int lane = tid & 31;
    const int warp_q = wid & 1;    // 2 q-groups of 32
    const int warp_n = wid >> 1;   // 4 n-groups of 16

    const uint32_t sA_u = smem_u32(&sA[0][0]);
    const uint32_t sB_u = smem_u32(&sB[0][0]);

    // global-load mapping: thread -> one A cp16 + one B cp16 per stage
    const int rowL = tid >> 2;             // 0..63
    const int ka   = (tid & 3) * 8;
    const __half* gA = g_xq + (size_t)(tile_m + rowL) * KDIM + ka;
    const __half* gB = g_cb + (size_t)(tile_n + rowL) * KDIM + ka;
    const uint32_t dA = sA_u + ((rowL * APITCH + ka) << 1);
    const uint32_t dB = sB_u + ((rowL * APITCH + ka) << 1);

    uint64_t NEG1 = pack2(-1.0f, -1.0f);
    uint64_t S[2][2][2], C[2][2][2];
    float chunk[2][2][4];
#pragma unroll
    for (int i = 0; i < 2; i++)
#pragma unroll
        for (int j = 0; j < 2; j++) {
            S[i][j][0] = 0ull; S[i][j][1] = 0ull;
            C[i][j][0] = 0ull; C[i][j][1] = 0ull;
#pragma unroll
            for (int k = 0; k < 4; k++) chunk[i][j][k] = 0.f;
        }

    // ldmatrix per-lane addressing (identical scheme to the R14 pass)
    const int arow  = warp_q * 32 + (lane & 15);
    const int akoff = (lane >> 4) << 3;
    const int bn    = warp_n * 16 + (lane & 7) + ((lane >> 4) << 3);
    const int bkoff = lane & 8;

    // prologue: stages 0..2
#pragma unroll
    for (int s = 0; s < NST - 1; s++) {
        const int k0 = s * BK;
        cp16(dA + s * A_STAGE_BYTES, gA + k0);
        cp16(dB + s * B_STAGE_BYTES, gB + k0);
        cp_commit();
    }

    for (int kt = 0; kt < NKITER; kt++) {
        // need stage kt complete; stages in flight beyond kt: min(2, 62-kt)
        if (kt < NKITER - 2)      asm volatile("cp.async.wait_group 2;\n");
        else if (kt < NKITER - 1) asm volatile("cp.async.wait_group 1;\n");
        else                      asm volatile("cp.async.wait_group 0;\n");
        __syncthreads();   // also protects buffer (kt+3)%4 (consumed at kt-1) for reuse

        // issue loads for stage kt+3 into the freed buffer, then compute
        if (kt + NST - 1 < NKITER) {
            const int nbuf = (kt + NST - 1) % NST;
            const int k0 = (kt + NST - 1) * BK;
            cp16(dA + nbuf * A_STAGE_BYTES, gA + k0);
            cp16(dB + nbuf * B_STAGE_BYTES, gB + k0);
            cp_commit();
        }

        const int buf = kt % NST;
        const uint32_t aB = sA_u + buf * A_STAGE_BYTES;
        const uint32_t bB = sB_u + buf * B_STAGE_BYTES;
#pragma unroll
        for (int ks = 0; ks < 2; ks++) {
            const int kh = ks * 16;
            uint32_t ra[2][4], rb[4];
            uint32_t a0 = aB + ((arow * APITCH + kh + akoff) << 1);
            ldsm4(ra[0], a0);
            ldsm4(ra[1], a0 + (16 * APITCH << 1));
            ldsm4(rb, bB + ((bn * APITCH + kh + bkoff) << 1));
#pragma unroll
            for (int mt = 0; mt < 2; mt++)
#pragma unroll
                for (int nt = 0; nt < 2; nt++)
                    mma16816(chunk[mt][nt], ra[mt], rb[nt * 2], rb[nt * 2 + 1]);
        }

        if ((kt % SEGLEN) == (SEGLEN - 1)) {
#pragma unroll
            for (int mt = 0; mt < 2; mt++)
#pragma unroll
                for (int nt = 0; nt < 2; nt++) {
                    kahan2(S[mt][nt][0], C[mt][nt][0],
                           pack2(chunk[mt][nt][0], chunk[mt][nt][1]), NEG1);
                    kahan2(S[mt][nt][1], C[mt][nt][1],
                           pack2(chunk[mt][nt][2], chunk[mt][nt][3]), NEG1);
#pragma unroll
                    for (int e = 0; e < 4; e++) chunk[mt][nt][e] = 0.f;
                }
        }
    }

    // -------- fused epilogue: distances + packed argmin --------
    for (int i = tid; i < BM; i += 256) { s_min0[i] = ~0ull; s_min1[i] = ~0ull; }
    __syncthreads();

    int   gm[2][2]; float vc2[2][2], vcn2[2][2]; bool mok[2][2];
#pragma unroll
    for (int nt = 0; nt < 2; nt++)
#pragma unroll
        for (int e1 = 0; e1 < 2; e1++) {
            int m = tile_n + warp_n * 16 + nt * 8 + (lane & 3) * 2 + e1;
            gm[nt][e1] = m;
            mok[nt][e1] = (m < MCW);
            vc2[nt][e1]  = mok[nt][e1] ? g_c2[m]  : 0.f;
            vcn2[nt][e1] = mok[nt][e1] ? g_cn2[m] : 0.f;
        }

#pragma unroll
    for (int mt = 0; mt < 2; mt++)
#pragma unroll
        for (int e2 = 0; e2 < 2; e2++) {
            const int qloc = warp_q * 32 + mt * 16 + (lane >> 2) + e2 * 8;
            const float x2v = g_x2[tile_m + qloc];
            const float xsv = g_xs[tile_m + qloc];
            unsigned long long b0 = ~0ull, b1 = ~0ull;
#pragma unroll
            for (int nt = 0; nt < 2; nt++) {
                const float2 sv = unpack2(S[mt][nt][e2]);
                const float2 cv = unpack2(C[mt][nt][e2]);
#pragma unroll
                for (int e1 = 0; e1 < 2; e1++) {
                    if (!mok[nt][e1]) continue;
                    const float xc = __fadd_rn(e1 ? sv.y : sv.x, e1 ? cv.y : cv.x);
                    const float d0 = __fsub_rn(__fadd_rn(x2v, vc2[nt][e1]), 2.0f * xc);
                    const float d1 = __fsub_rn(__fadd_rn(x2v, vcn2[nt][e1]),
                                               2.0f * __fsub_rn(xsv, xc));
                    unsigned long long p0 = ((unsigned long long)fkey(d0) << 32) | (uint32_t)gm[nt][e1];
                    unsigned long long p1 = ((unsigned long long)fkey(d1) << 32) | (uint32_t)gm[nt][e1];
                    if (p0 < b0) b0 = p0;
                    if (p1 < b1) b1 = p1;
                }
            }
            atomicMin_block(&s_min0[qloc], b0);
            atomicMin_block(&s_min1[qloc], b1);
        }
    __syncthreads();

    if (tid < BM) {
        atomicMin(&g_m0[tile_m + tid], s_min0[tid]);
        atomicMin(&g_m1[tile_m + tid], s_min1[tid]);
    }
}

// ---------------- kernel 4: finalize -> bits ----------------
__global__ void finalize_kernel(float* __restrict__ out) {
    const int q = blockIdx.x * blockDim.x + threadIdx.x;
    if (q >= NQ) return;
    const unsigned long long v0 = g_m0[q];
    const unsigned long long v1 = g_m1[q];
    const uint32_t k0 = (uint32_t)(v0 >> 32);
    const uint32_t k1 = (uint32_t)(v1 >> 32);
    // [d0, d1, d1, d0] concat: d0 block first -> d0 wins ties
    const int res = (k0 <= k1) ? (int)(v0 & 0xFFFFFFFFu) : MCW + (int)(v1 & 0xFFFFFFFFu);
#pragma unroll
    for (int b = 0; b < 32; b++)
        out[q * 32 + b] = (float)((res >> b) & 1);
}

// ---------------- launch ----------------
extern "C" void kernel_launch(void* const* d_in, const int* in_sizes, int n_in,
                              void* d_out, int out_size) {
    // Identify inputs by element count, NOT by position:
    //   x    : 64*2*126*128   = 2,064,384
    //   data : 16001*2*126*8  = 32,258,016
    const void* x    = d_in[0];
    const void* data = d_in[1];
    if (n_in >= 2 && in_sizes[0] > in_sizes[1]) {
        x    = d_in[1];
        data = d_in[0];
    }
    float* out = (float*)d_out;   // [64,512], float 0.0/1.0

    detect_kernel<<<4, 256>>>((const uint32_t*)x, (const uint32_t*)data);
    build_xq_kernel<<<NQ, 256>>>(x);
    prep_cb_kernel<<<MCW, 128>>>(data);
    gemm_kernel<<<dim3(NQ / BM, MPAD / BN), 256>>>();   // 4th launch -> profiled
    finalize_kernel<<<4, 256>>>(out);
}

// round 17
// speedup vs baseline: 1.6347x; 1.0086x over previous
#include <cuda_runtime.h>
#include <cuda_fp16.h>
#include <cuda_bf16.h>
#include <cstdint>

// ---------------- problem constants ----------------
#define NQ      1024      // 64 batches * 16 slots
#define MCW     16001     // codebook rows
#define MPAD    16128     // 126 * 128
#define KDIM    2016
#define BM      64        // q rows per CTA
#define BN      128       // m cols per CTA
#define BK      32        // halfs per k stage
#define NKITER  63        // 2016 / 32
#define SEGLEN  3         // k-iters per accumulation segment (63 = 21*3)
#define NST     3         // pipeline stages

// dtype codes
#define DT_F16  0
#define DT_BF16 1
#define DT_F32  2

// ---------------- scratch (static device memory; no allocs) ----------------
__device__ int    g_dt_x;
__device__ int    g_dt_d;
__device__ __half g_xq[NQ * KDIM];           // permuted queries, k-major
__device__ __half g_cb[(size_t)MPAD * KDIM]; // codebook fp16 (rows >= MCW stay zero)
__device__ float  g_xs[NQ];
__device__ float  g_x2[NQ];
__device__ float  g_c2[MPAD];
__device__ float  g_cn2[MPAD];
__device__ unsigned long long g_m0[NQ];      // packed (key(d0)<<32 | idx) running min
__device__ unsigned long long g_m1[NQ];      // packed (key(d1)<<32 | idx) running min

// ---------------- small PTX helpers ----------------
__device__ __forceinline__ uint32_t smem_u32(const void* p) {
    uint32_t a;
    asm("{ .reg .u64 t; cvta.to.shared.u64 t, %1; cvt.u32.u64 %0, t; }" : "=r"(a) : "l"(p));
    return a;
}
__device__ __forceinline__ void cp16(uint32_t dst, const void* src) {
    asm volatile("cp.async.cg.shared.global [%0], [%1], 16;\n" :: "r"(dst), "l"(src));
}
__device__ __forceinline__ void cp_commit() { asm volatile("cp.async.commit_group;\n"); }
__device__ __forceinline__ void ldsm4(uint32_t* r, uint32_t addr) {
    asm volatile("ldmatrix.sync.aligned.m8n8.x4.shared.b16 {%0,%1,%2,%3}, [%4];"
                 : "=r"(r[0]), "=r"(r[1]), "=r"(r[2]), "=r"(r[3]) : "r"(addr));
}
__device__ __forceinline__ void mma16816(float* d, const uint32_t* a, uint32_t b0, uint32_t b1) {
    asm volatile("mma.sync.aligned.m16n8k16.row.col.f32.f16.f16.f32 "
                 "{%0,%1,%2,%3}, {%4,%5,%6,%7}, {%8,%9}, {%0,%1,%2,%3};\n"
                 : "+f"(d[0]), "+f"(d[1]), "+f"(d[2]), "+f"(d[3])
                 : "r"(a[0]), "r"(a[1]), "r"(a[2]), "r"(a[3]), "r"(b0), "r"(b1));
}
// order-preserving float->u32 key (monotone for all floats incl. negatives)
__device__ __forceinline__ uint32_t fkey(float f) {
    uint32_t b = __float_as_uint(f);
    return (b & 0x80000000u) ? ~b : (b | 0x80000000u);
}

// ---- packed f32x2 Kahan (bit-identical to the scalar __fsub_rn/__fadd_rn fold:
//      fma.rn(a,-1,b) has one rounding of b-a, exactly like sub.rn) ----
__device__ __forceinline__ uint64_t pack2(float lo, float hi) {
    uint64_t p;
    asm("mov.b64 %0, {%1, %2};" : "=l"(p) : "r"(__float_as_uint(lo)), "r"(__float_as_uint(hi)));
    return p;
}
__device__ __forceinline__ float2 unpack2(uint64_t p) {
    uint32_t lo, hi;
    asm("mov.b64 {%0, %1}, %2;" : "=r"(lo), "=r"(hi) : "l"(p));
    return make_float2(__uint_as_float(lo), __uint_as_float(hi));
}
__device__ __forceinline__ void kahan2(uint64_t& s, uint64_t& c, uint64_t ch, uint64_t neg1) {
    uint64_t y, t, d;
    asm("fma.rn.f32x2 %0, %1, %2, %3;" : "=l"(y) : "l"(c), "l"(neg1), "l"(ch));  // y = ch - c
    asm("add.rn.f32x2 %0, %1, %2;"     : "=l"(t) : "l"(s), "l"(y));              // t = s + y
    asm("fma.rn.f32x2 %0, %1, %2, %3;" : "=l"(d) : "l"(s), "l"(neg1), "l"(t));   // d = t - s
    asm("fma.rn.f32x2 %0, %1, %2, %3;" : "=l"(c) : "l"(y), "l"(neg1), "l"(d));   // c = d - y
    s = t;
}

// ---------------- generic 8-element load ----------------
__device__ __forceinline__ void load8(const void* p, size_t off, int dt, float* f) {
    if (dt == DT_F32) {
        const float4* q = (const float4*)((const float*)p + off);
        float4 v0 = q[0], v1 = q[1];
        f[0]=v0.x; f[1]=v0.y; f[2]=v0.z; f[3]=v0.w;
        f[4]=v1.x; f[5]=v1.y; f[6]=v1.z; f[7]=v1.w;
    } else if (dt == DT_F16) {
        uint4 v = *(const uint4*)((const __half*)p + off);
        const __half2* hp = (const __half2*)&v;
#pragma unroll
        for (int i = 0; i < 4; i++) {
            float2 g = __half22float2(hp[i]);
            f[2*i] = g.x; f[2*i+1] = g.y;
        }
    } else {
        uint4 v = *(const uint4*)((const __nv_bfloat16*)p + off);
        const __nv_bfloat162* hp = (const __nv_bfloat162*)&v;
#pragma unroll
        for (int i = 0; i < 4; i++) {
            float2 g = __bfloat1622float2(hp[i]);
            f[2*i] = g.x; f[2*i+1] = g.y;
        }
    }
}

// ---------------- kernel 0: dtype detection + packed-min reset ----------------
__global__ void detect_kernel(const uint32_t* x, const uint32_t* d) {
    const int gi = blockIdx.x * blockDim.x + threadIdx.x;
    if (gi < NQ) { g_m0[gi] = ~0ull; g_m1[gi] = ~0ull; }
    if (gi == 0) {
        const uint32_t* ps[2] = {x, d};
        int* outs[2] = {&g_dt_x, &g_dt_d};
        for (int a = 0; a < 2; a++) {
            uint32_t lowmax = 0, highmax = 0;
            for (int i = 0; i < 64; i++) {
                uint32_t w = ps[a][i];
                uint32_t lo = w & 0xFFFFu, hi = w >> 16;
                if (lo > lowmax) lowmax = lo;
                if (hi > highmax) highmax = hi;
            }
            int dt;
            if (lowmax >= 0x4000u)       dt = DT_F32;
            else if (highmax >= 0x3C00u) dt = DT_BF16;
            else                         dt = DT_F16;
            *outs[a] = dt;
        }
    }
}

// ---------------- kernel 1: permute x -> xq (fp16), compute xs/x2 ----------------
__global__ __launch_bounds__(256) void build_xq_kernel(const void* xraw) {
    const int q = blockIdx.x;
    const int b = q >> 4, slot = q & 15;
    const int t = threadIdx.x;
    const int dt = g_dt_x;
    float s = 0.f, s2 = 0.f;
    if (t < 252) {
        const int ch = t / 126, row = t % 126;
        const size_t off = (size_t)b * 32256 + ch * 16128 + row * 128 + slot * 8;
        float f[8];
        load8(xraw, off, dt, f);
        __half h[8];
#pragma unroll
        for (int i = 0; i < 8; i++) {
            h[i] = __float2half_rn(f[i]);
            s  += f[i];
            s2 += f[i] * f[i];
        }
        *(uint4*)(g_xq + (size_t)q * KDIM + t * 8) = *(const uint4*)h;
    }
    __shared__ float r0[256], r1[256];
    r0[t] = s; r1[t] = s2; __syncthreads();
    for (int st = 128; st > 0; st >>= 1) {
        if (t < st) { r0[t] += r0[t + st]; r1[t] += r1[t + st]; }
        __syncthreads();
    }
    if (t == 0) { g_xs[q] = r0[0]; g_x2[q] = r1[0]; }
}

// ---------------- kernel 2: codebook -> fp16 + per-row c2/cn2 ----------------
__global__ __launch_bounds__(128) void prep_cb_kernel(const void* draw) {
    const int m = blockIdx.x;
    const int t = threadIdx.x;
    const int dt = g_dt_d;
    __half* dst = g_cb + (size_t)m * KDIM;
    float s2 = 0.f, sn2 = 0.f;
    for (int v = t; v < 252; v += 128) {
        float f[8];
        load8(draw, (size_t)m * KDIM + v * 8, dt, f);
        __half h[8];
#pragma unroll
        for (int i = 0; i < 8; i++) {
            h[i] = __float2half_rn(f[i]);
            s2 += f[i] * f[i];
            float g1 = 1.0f - f[i];
            sn2 += g1 * g1;
        }
        *(uint4*)(dst + v * 8) = *(const uint4*)h;
    }
    __shared__ float r0[128], r1[128];
    r0[t] = s2; r1[t] = sn2; __syncthreads();
    for (int st = 64; st > 0; st >>= 1) {
        if (t < st) { r0[t] += r0[t + st]; r1[t] += r1[t + st]; }
        __syncthreads();
    }
    if (t == 0) { g_c2[m] = r0[0]; g_cn2[m] = r1[0]; }
}

// ---------------- kernel 3: GEMM + fused distance/argmin ----------------
// CTA tile 64q x 128m, 256 threads / 8 warps, warp tile 32q x 32m (2q x 4n
// warp grid -- B addressing validated in the R11 pass), 3-stage cp.async,
// 2 CTAs/SM. Per warp per k16: 2A+2B ldsm + 8 MMA (vs 2A+1B+4 before):
// 33% less L1 traffic and half the fold/addressing per MMA. Numerics
// bit-identical: BK=32, SEGLEN=3 segments, packed-f32x2 Kahan fold.
#define APITCH 40
#define A_STAGE (BM * APITCH)             // 2560 halfs
#define B_STAGE (BN * APITCH)             // 5120 halfs
#define A_STAGE_BYTES (A_STAGE * 2)       // 5120 B
#define B_STAGE_BYTES (B_STAGE * 2)       // 10240 B

__global__ __launch_bounds__(256, 2) void gemm_kernel() {
    __shared__ __half sA[NST][A_STAGE];
    __shared__ __half sB[NST][B_STAGE];
    __shared__ unsigned long long s_min0[BM];
    __shared__ unsigned long long s_min1[BM];

    const int tile_m = blockIdx.x * BM;    // q tile (x fastest: q-tiles share cb rows in L2)
    const int tile_n = blockIdx.y * BN;    // m tile
    const int tid  = threadIdx.x;
    const int wid  = tid >> 5;
    const int lane = tid & 31;
    const int warp_q = wid & 1;    // 2 q-groups of 32
    const int warp_n = wid >> 1;   // 4 n-groups of 32

    const uint32_t sA_u = smem_u32(&sA[0][0]);
    const uint32_t sB_u = smem_u32(&sB[0][0]);

    // global-load mapping: thread -> 1 A row chunk + 2 B row chunks per stage
    const int rowL = tid >> 2;             // 0..63
    const int ka   = (tid & 3) * 8;
    const __half* gA  = g_xq + (size_t)(tile_m + rowL) * KDIM + ka;
    const __half* gB0 = g_cb + (size_t)(tile_n + rowL) * KDIM + ka;
    const __half* gB1 = g_cb + (size_t)(tile_n + 64 + rowL) * KDIM + ka;
    const uint32_t dA  = sA_u + ((rowL * APITCH + ka) << 1);
    const uint32_t dB0 = sB_u + ((rowL * APITCH + ka) << 1);
    const uint32_t dB1 = sB_u + (((64 + rowL) * APITCH + ka) << 1);

    uint64_t NEG1 = pack2(-1.0f, -1.0f);
    uint64_t S[2][4][2], C[2][4][2];
    float chunk[2][4][4];
#pragma unroll
    for (int i = 0; i < 2; i++)
#pragma unroll
        for (int j = 0; j < 4; j++) {
            S[i][j][0] = 0ull; S[i][j][1] = 0ull;
            C[i][j][0] = 0ull; C[i][j][1] = 0ull;
#pragma unroll
            for (int k = 0; k < 4; k++) chunk[i][j][k] = 0.f;
        }

    // ldmatrix per-lane addressing (A as in R14 pass, B as in R11 pass)
    const int arow  = warp_q * 32 + (lane & 15);
    const int akoff = (lane >> 4) << 3;
    const int bn    = warp_n * 32 + (lane & 7) + ((lane >> 4) << 3);
    const int bkoff = lane & 8;

    // prologue: stages 0, 1
#pragma unroll
    for (int s = 0; s < NST - 1; s++) {
        const int k0 = s * BK;
        cp16(dA  + s * A_STAGE_BYTES, gA  + k0);
        cp16(dB0 + s * B_STAGE_BYTES, gB0 + k0);
        cp16(dB1 + s * B_STAGE_BYTES, gB1 + k0);
        cp_commit();
    }

    for (int kt = 0; kt < NKITER; kt++) {
        // pending groups before this wait: G_kt, G_{kt+1}; at kt==62 only G_62.
        if (kt < NKITER - 1) asm volatile("cp.async.wait_group 1;\n");
        else                 asm volatile("cp.async.wait_group 0;\n");
        __syncthreads();   // also protects buffer (kt+2)%3 (consumed at kt-1) for reuse

        // issue loads for stage kt+2 into the freed buffer, then compute
        if (kt + NST - 1 < NKITER) {
            const int nbuf = (kt + NST - 1) % NST;
            const int k0 = (kt + NST - 1) * BK;
            cp16(dA  + nbuf * A_STAGE_BYTES, gA  + k0);
            cp16(dB0 + nbuf * B_STAGE_BYTES, gB0 + k0);
            cp16(dB1 + nbuf * B_STAGE_BYTES, gB1 + k0);
            cp_commit();
        }

        const int buf = kt % NST;
        const uint32_t aB = sA_u + buf * A_STAGE_BYTES;
        const uint32_t bB = sB_u + buf * B_STAGE_BYTES;
#pragma unroll
        for (int ks = 0; ks < 2; ks++) {
            const int kh = ks * 16;
            uint32_t ra[2][4], rb[2][4];
            uint32_t a0 = aB + ((arow * APITCH + kh + akoff) << 1);
            ldsm4(ra[0], a0);
            ldsm4(ra[1], a0 + (16 * APITCH << 1));
            uint32_t b0 = bB + ((bn * APITCH + kh + bkoff) << 1);
            ldsm4(rb[0], b0);
            ldsm4(rb[1], b0 + (16 * APITCH << 1));
#pragma unroll
            for (int mt = 0; mt < 2; mt++)
#pragma unroll
                for (int nt = 0; nt < 4; nt++)
                    mma16816(chunk[mt][nt], ra[mt],
                             rb[nt >> 1][(nt & 1) * 2], rb[nt >> 1][(nt & 1) * 2 + 1]);
        }

        if ((kt % SEGLEN) == (SEGLEN - 1)) {
#pragma unroll
            for (int mt = 0; mt < 2; mt++)
#pragma unroll
                for (int nt = 0; nt < 4; nt++) {
                    kahan2(S[mt][nt][0], C[mt][nt][0],
                           pack2(chunk[mt][nt][0], chunk[mt][nt][1]), NEG1);
                    kahan2(S[mt][nt][1], C[mt][nt][1],
                           pack2(chunk[mt][nt][2], chunk[mt][nt][3]), NEG1);
#pragma unroll
                    for (int e = 0; e < 4; e++) chunk[mt][nt][e] = 0.f;
                }
        }
    }

    // -------- fused epilogue: distances + packed argmin --------
    for (int i = tid; i < BM; i += 256) { s_min0[i] = ~0ull; s_min1[i] = ~0ull; }
    __syncthreads();

    int   gm[4][2]; float vc2[4][2], vcn2[4][2]; bool mok[4][2];
#pragma unroll
    for (int nt = 0; nt < 4; nt++)
#pragma unroll
        for (int e1 = 0; e1 < 2; e1++) {
            int m = tile_n + warp_n * 32 + nt * 8 + (lane & 3) * 2 + e1;
            gm[nt][e1] = m;
            mok[nt][e1] = (m < MCW);
            vc2[nt][e1]  = mok[nt][e1] ? g_c2[m]  : 0.f;
            vcn2[nt][e1] = mok[nt][e1] ? g_cn2[m] : 0.f;
        }

#pragma unroll
    for (int mt = 0; mt < 2; mt++)
#pragma unroll
        for (int e2 = 0; e2 < 2; e2++) {
            const int qloc = warp_q * 32 + mt * 16 + (lane >> 2) + e2 * 8;
            const float x2v = g_x2[tile_m + qloc];
            const float xsv = g_xs[tile_m + qloc];
            unsigned long long b0 = ~0ull, b1 = ~0ull;
#pragma unroll
            for (int nt = 0; nt < 4; nt++) {
                const float2 sv = unpack2(S[mt][nt][e2]);
                const float2 cv = unpack2(C[mt][nt][e2]);
#pragma unroll
                for (int e1 = 0; e1 < 2; e1++) {
                    if (!mok[nt][e1]) continue;
                    const float xc = __fadd_rn(e1 ? sv.y : sv.x, e1 ? cv.y : cv.x);
                    const float d0 = __fsub_rn(__fadd_rn(x2v, vc2[nt][e1]), 2.0f * xc);
                    const float d1 = __fsub_rn(__fadd_rn(x2v, vcn2[nt][e1]),
                                               2.0f * __fsub_rn(xsv, xc));
                    unsigned long long p0 = ((unsigned long long)fkey(d0) << 32) | (uint32_t)gm[nt][e1];
                    unsigned long long p1 = ((unsigned long long)fkey(d1) << 32) | (uint32_t)gm[nt][e1];
                    if (p0 < b0) b0 = p0;
                    if (p1 < b1) b1 = p1;
                }
            }
            atomicMin_block(&s_min0[qloc], b0);
            atomicMin_block(&s_min1[qloc], b1);
        }
    __syncthreads();

    if (tid < BM) {
        atomicMin(&g_m0[tile_m + tid], s_min0[tid]);
        atomicMin(&g_m1[tile_m + tid], s_min1[tid]);
    }
}

// ---------------- kernel 4: finalize -> bits ----------------
__global__ void finalize_kernel(float* __restrict__ out) {
    const int q = blockIdx.x * blockDim.x + threadIdx.x;
    if (q >= NQ) return;
    const unsigned long long v0 = g_m0[q];
    const unsigned long long v1 = g_m1[q];
    const uint32_t k0 = (uint32_t)(v0 >> 32);
    const uint32_t k1 = (uint32_t)(v1 >> 32);
    // [d0, d1, d1, d0] concat: d0 block first -> d0 wins ties
    const int res = (k0 <= k1) ? (int)(v0 & 0xFFFFFFFFu) : MCW + (int)(v1 & 0xFFFFFFFFu);
#pragma unroll
    for (int b = 0; b < 32; b++)
        out[q * 32 + b] = (float)((res >> b) & 1);
}

// ---------------- launch ----------------
extern "C" void kernel_launch(void* const* d_in, const int* in_sizes, int n_in,
                              void* d_out, int out_size) {
    // Identify inputs by element count, NOT by position:
    //   x    : 64*2*126*128   = 2,064,384
    //   data : 16001*2*126*8  = 32,258,016
    const void* x    = d_in[0];
    const void* data = d_in[1];
    if (n_in >= 2 && in_sizes[0] > in_sizes[1]) {
        x    = d_in[1];
        data = d_in[0];
    }
    float* out = (float*)d_out;   // [64,512], float 0.0/1.0

    detect_kernel<<<4, 256>>>((const uint32_t*)x, (const uint32_t*)data);
    build_xq_kernel<<<NQ, 256>>>(x);
    prep_cb_kernel<<<MCW, 128>>>(data);
    gemm_kernel<<<dim3(NQ / BM, MPAD / BN), 256>>>();   // 4th launch -> profiled
    finalize_kernel<<<4, 256>>>(out);
}